// round 12
// baseline (speedup 1.0000x reference)
#include <cuda_runtime.h>
#include <cuda_fp16.h>
#include <cstdint>

#define NB 256
#define NT 512
#define NC 64
#define NH 64
#define HP 72          // halves per smem row (pad: 144B rows, conflict-free ldmatrix)
#define HPB 144        // bytes per smem row

// Projected q,k,v scratch in fp16 (11-bit significand == tf32).
// q pre-scaled by 0.125*log2(e): softmax exp is ex2 (base-2 domain).
// g_q/g_k rows use a fragment-native WITHIN-ROW PERMUTATION (identical for
// both, so the QK contraction is unchanged). g_v stays logical row-major.
__device__ __half g_q[(size_t)NB * NT * NH];
__device__ __half g_k[(size_t)NB * NT * NH];
__device__ __half g_v[(size_t)NB * NT * NH];

__device__ __forceinline__ uint32_t smem_u32(const void* p) {
    uint32_t a;
    asm("{ .reg .u64 t; cvta.to.shared.u64 t, %1; cvt.u32.u64 %0, t; }"
        : "=r"(a) : "l"(p));
    return a;
}
__device__ __forceinline__ uint32_t packh2(float lo, float hi) {
    __half2 h = __floats2half2_rn(lo, hi);
    return *reinterpret_cast<uint32_t*>(&h);
}
__device__ __forceinline__ uint32_t ex2h2(uint32_t s) {   // 2 exps, 1 MUFU op
    uint32_t r;
    asm("ex2.approx.f16x2 %0, %1;" : "=r"(r) : "r"(s));
    return r;
}
__device__ __forceinline__ void mma_f16(float c[4], const uint32_t a[4],
                                        uint32_t b0, uint32_t b1) {
    asm volatile(
        "mma.sync.aligned.m16n8k16.row.col.f32.f16.f16.f32 "
        "{%0,%1,%2,%3}, {%4,%5,%6,%7}, {%8,%9}, {%0,%1,%2,%3};"
        : "+f"(c[0]), "+f"(c[1]), "+f"(c[2]), "+f"(c[3])
        : "r"(a[0]), "r"(a[1]), "r"(a[2]), "r"(a[3]), "r"(b0), "r"(b1));
}
__device__ __forceinline__ void ldsm4(uint32_t r[4], uint32_t addr) {
    asm volatile("ldmatrix.sync.aligned.m8n8.x4.shared.b16 {%0,%1,%2,%3}, [%4];"
        : "=r"(r[0]), "=r"(r[1]), "=r"(r[2]), "=r"(r[3]) : "r"(addr));
}
__device__ __forceinline__ void ldsm4t(uint32_t r[4], uint32_t addr) {
    asm volatile("ldmatrix.sync.aligned.m8n8.x4.trans.shared.b16 {%0,%1,%2,%3}, [%4];"
        : "=r"(r[0]), "=r"(r[1]), "=r"(r[2]), "=r"(r[3]) : "r"(addr));
}
// A (row-major m16k16): m0=(r0..7,k0..7) m1=(r8..15,k0..7) m2=(r0..7,k8..15) m3=(r8..15,k8..15)
__device__ __forceinline__ uint32_t addrA(uint32_t base, int lane, int row0, int k0) {
    return base + (uint32_t)(row0 + (lane & 15)) * HPB
                + (uint32_t)(k0 * 2 + ((lane >> 4) << 4));
}
// B from K rows (row-major [n][k], no trans)
__device__ __forceinline__ uint32_t addrB(uint32_t base, int lane, int n0, int k0) {
    return base + (uint32_t)(n0 + (lane & 7) + ((lane >> 4) << 3)) * HPB
                + (uint32_t)(k0 * 2 + (((lane >> 3) & 1) << 4));
}
// B from V/W rows (row-major [k][n], trans)
__device__ __forceinline__ uint32_t addrT(uint32_t base, int lane, int s0, int n0) {
    return base + (uint32_t)(s0 + (lane & 7) + (((lane >> 3) & 1) << 3)) * HPB
                + (uint32_t)(n0 * 2 + ((lane >> 4) << 4));
}
#define CP_ASYNC16(dst, src) \
    asm volatile("cp.async.cg.shared.global [%0], [%1], 16;" \
                 :: "r"((uint32_t)(dst)), "l"(src))
#define CP_COMMIT() asm volatile("cp.async.commit_group;" ::: "memory")
#define CP_WAIT0()  asm volatile("cp.async.wait_group 0;" ::: "memory")

__device__ __forceinline__ void load_tile64(uint32_t dst, const __half* src, int tid) {
    #pragma unroll
    for (int m = 0; m < 4; m++) {
        int idx = tid + 128 * m;
        int r = idx >> 3, c = idx & 7;
        CP_ASYNC16(dst + r * HPB + c * 16, src + r * NH + c * 8);
    }
}

// attn smem
#define K0OFF 0
#define K1OFF 9216
#define V0OFF 18432
#define V1OFF 27648
#define PQOFF 36864      // Q staging (frags lifted to regs once)
#define SMEM2 55296
// proj: x rows 0-127 (reused as V store staging), W_sel rows 128+64*sel
#define SMEM1 46080

// ---------------------------------------------------------------------------
// Kernel 1: q,k,v = x @ {Wq,Wk,Wv}. 512 CTAs x two 128-row halves;
// W in smem once per CTA. Wq pre-scaled by 0.125*log2(e).
// Q/K stored with fragment-native within-row permutation (coalesced 16B
// stores); V restaged through the dead x smem region for coalesced stores.
// ---------------------------------------------------------------------------
__global__ void __launch_bounds__(128, 4) proj_kernel(
    const float* __restrict__ x,
    const float* __restrict__ wk,
    const float* __restrict__ wq,
    const float* __restrict__ wv)
{
    extern __shared__ char smraw[];
    __half* smh = (__half*)smraw;
    const uint32_t sb = smem_u32(smraw);
    const int tid = threadIdx.x;
    const int w = tid >> 5, lane = tid & 31, g = lane >> 2, tig = lane & 3;

    const float* W[3] = { wq, wk, wv };
    #pragma unroll
    for (int sel = 0; sel < 3; sel++) {
        __half* ws = smh + (128 + 64 * sel) * HP;
        const float scl = (sel == 0) ? 0.125f * 1.44269504088896f : 1.0f;
        #pragma unroll
        for (int m = 0; m < 8; m++) {
            int idx = tid + 128 * m;
            int r = idx >> 4, f4 = idx & 15;
            float4 v = *(const float4*)(W[sel] + r * NH + f4 * 4);
            *(__half2*)(ws + r * HP + f4 * 4)     = __floats2half2_rn(v.x * scl, v.y * scl);
            *(__half2*)(ws + r * HP + f4 * 4 + 2) = __floats2half2_rn(v.z * scl, v.w * scl);
        }
    }

    #pragma unroll 1
    for (int h = 0; h < 2; h++) {
        const size_t r0 = (size_t)blockIdx.x * 256 + (size_t)h * 128;
        __syncthreads();   // h=0: W ready; h>0: prior V-staging copies done
        #pragma unroll
        for (int m = 0; m < 16; m++) {
            int idx = tid + 128 * m;
            int r = idx >> 4, f4 = idx & 15;
            float4 v = *(const float4*)(x + (r0 + r) * NC + f4 * 4);
            *(__half2*)(smh + r * HP + f4 * 4)     = __floats2half2_rn(v.x, v.y);
            *(__half2*)(smh + r * HP + f4 * 4 + 2) = __floats2half2_rn(v.z, v.w);
        }
        __syncthreads();

        uint32_t xa[2][4][4];
        #pragma unroll
        for (int mt = 0; mt < 2; mt++)
            #pragma unroll
            for (int t = 0; t < 4; t++)
                ldsm4(xa[mt][t], addrA(sb, lane, 32 * w + 16 * mt, 16 * t));

        #pragma unroll
        for (int sel = 0; sel < 3; sel++) {
            const uint32_t wb = sb + (uint32_t)(128 + 64 * sel) * HPB;
            float cc[2][8][4] = {};
            #pragma unroll
            for (int t = 0; t < 4; t++)
                #pragma unroll
                for (int np = 0; np < 4; np++) {
                    uint32_t br[4];
                    ldsm4t(br, addrT(wb, lane, 16 * t, 16 * np));
                    #pragma unroll
                    for (int mt = 0; mt < 2; mt++) {
                        mma_f16(cc[mt][2 * np],     xa[mt][t], br[0], br[1]);
                        mma_f16(cc[mt][2 * np + 1], xa[mt][t], br[2], br[3]);
                    }
                }

            if (sel < 2) {
                // Q/K: permuted within-row layout -> coalesced 16B stores.
                __half* G = (sel == 0) ? g_q : g_k;
                #pragma unroll
                for (int mt = 0; mt < 2; mt++) {
                    const size_t ra = r0 + 32 * w + 16 * mt + g;
                    uint32_t lo[8], hi[8];
                    #pragma unroll
                    for (int n = 0; n < 8; n++) {
                        lo[n] = packh2(cc[mt][n][0], cc[mt][n][1]);
                        hi[n] = packh2(cc[mt][n][2], cc[mt][n][3]);
                    }
                    char* d0 = (char*)(G + ra * NH) + tig * 32;
                    char* d1 = (char*)(G + (ra + 8) * NH) + tig * 32;
                    *(uint4*)d0        = make_uint4(lo[0], lo[1], lo[2], lo[3]);
                    *(uint4*)(d0 + 16) = make_uint4(lo[4], lo[5], lo[6], lo[7]);
                    *(uint4*)d1        = make_uint4(hi[0], hi[1], hi[2], hi[3]);
                    *(uint4*)(d1 + 16) = make_uint4(hi[4], hi[5], hi[6], hi[7]);
                }
            } else {
                // V: logical layout; restage through dead x region.
                __syncthreads();
                #pragma unroll
                for (int mt = 0; mt < 2; mt++) {
                    const int rl = 32 * w + 16 * mt + g;
                    #pragma unroll
                    for (int n = 0; n < 8; n++) {
                        *(__half2*)(smh + rl * HP + 8 * n + 2 * tig) =
                            __floats2half2_rn(cc[mt][n][0], cc[mt][n][1]);
                        *(__half2*)(smh + (rl + 8) * HP + 8 * n + 2 * tig) =
                            __floats2half2_rn(cc[mt][n][2], cc[mt][n][3]);
                    }
                }
                __syncthreads();
                #pragma unroll
                for (int i = 0; i < 8; i++) {
                    int c = tid + 128 * i;
                    int r = c >> 3, o = c & 7;
                    uint4 val = *(uint4*)(smraw + r * HPB + o * 16);
                    *(uint4*)(g_v + (r0 + r) * NH + o * 8) = val;
                }
            }
        }
    }
}

// ---------------------------------------------------------------------------
// Kernel 2: flash attention — R11 structure, plus: row sums computed ON THE
// TENSOR PIPE via lsc += P @ ones_B (constant register B-fragment, no ldsm).
// Deletes all f16->f32 unpacks + FADDs for lsum (~128 issues/warp-tile) and
// the epilogue shfl_xor tree. P used for PV and lsum is bit-identical.
// ---------------------------------------------------------------------------
__global__ void __launch_bounds__(128, 3) attn_kernel(float* __restrict__ out)
{
    extern __shared__ char smraw[];
    const uint32_t sb = smem_u32(smraw);
    const int tid = threadIdx.x;
    const int w = tid >> 5, lane = tid & 31, g = lane >> 2, tig = lane & 3;
    const int qt = (gridDim.x - 1) - blockIdx.x;   // big causal tiles first
    const int b = blockIdx.y;
    const int nt = 2 * qt + 2;
    const size_t qbase = ((size_t)b * NT + (size_t)qt * 128) * NH;
    const __half* kp0 = g_k + (size_t)b * NT * NH;
    const __half* vp0 = g_v + (size_t)b * NT * NH;

    // ones B-fragment (k16n8, column 0 all ones): lanes in group g==0 hold
    // column 0 -> half2(1,1); all other lanes hold zero columns.
    const uint32_t one_b = (g == 0) ? 0x3C003C00u : 0u;

    load_tile64(sb + K0OFF, kp0, tid);
    load_tile64(sb + V0OFF, vp0, tid);
    CP_COMMIT();

    // stage Q (fp16, pre-scaled, permuted rows copied verbatim)
    #pragma unroll
    for (int m = 0; m < 8; m++) {
        int idx = tid + 128 * m;
        int r = idx >> 3, c = idx & 7;
        *(uint4*)(smraw + PQOFF + r * HPB + c * 16) =
            *(const uint4*)(g_q + qbase + r * NH + c * 8);
    }
    __syncthreads();

    uint32_t qa[2][4][4];
    #pragma unroll
    for (int mt = 0; mt < 2; mt++)
        #pragma unroll
        for (int t = 0; t < 4; t++)
            ldsm4(qa[mt][t], addrA(sb + PQOFF, lane, 32 * w + 16 * mt, 16 * t));

    float oc[2][8][4] = {};
    float lsc[2][4] = {};                 // lsum C-frags: col0 = row sums
    const int row0q = qt * 128 + 32 * w + g;

    for (int j = 0; j < nt; j++) {
        CP_WAIT0();
        __syncthreads();
        const int cur = j & 1;
        if (j + 1 < nt) {
            load_tile64(sb + (cur ? K0OFF : K1OFF), kp0 + (size_t)(j + 1) * 64 * NH, tid);
            load_tile64(sb + (cur ? V0OFF : V1OFF), vp0 + (size_t)(j + 1) * 64 * NH, tid);
            CP_COMMIT();
        }
        const uint32_t Kb = sb + (cur ? K1OFF : K0OFF);
        const uint32_t Vb = sb + (cur ? V1OFF : V0OFF);
        const int jbase = j * 64;
        const bool needMask = (j >= 2 * qt);

        uint32_t pl[2][8], ph[2][8];
        #pragma unroll
        for (int np = 0; np < 4; np++) {
            float sc[2][2][4] = {};
            #pragma unroll
            for (int t = 0; t < 4; t++) {
                uint32_t kr[4];
                ldsm4(kr, addrB(Kb, lane, 16 * np, 16 * t));
                mma_f16(sc[0][0], qa[0][t], kr[0], kr[1]);
                mma_f16(sc[0][1], qa[0][t], kr[2], kr[3]);
                mma_f16(sc[1][0], qa[1][t], kr[0], kr[1]);
                mma_f16(sc[1][1], qa[1][t], kr[2], kr[3]);
            }
            #pragma unroll
            for (int mt = 0; mt < 2; mt++) {
                const int r0 = row0q + 16 * mt, r1 = r0 + 8;
                #pragma unroll
                for (int hh = 0; hh < 2; hh++) {
                    const int nn = 2 * np + hh;
                    const int col = jbase + 8 * nn + 2 * tig;
                    // pack scores to f16x2, exp2 both halves in ONE MUFU op
                    uint32_t p01 = ex2h2(packh2(sc[mt][hh][0], sc[mt][hh][1]));
                    uint32_t p23 = ex2h2(packh2(sc[mt][hh][2], sc[mt][hh][3]));
                    if (needMask) {
                        p01 &= (col > r0 ? 0u : 0x0000FFFFu) |
                               (col + 1 > r0 ? 0u : 0xFFFF0000u);
                        p23 &= (col > r1 ? 0u : 0x0000FFFFu) |
                               (col + 1 > r1 ? 0u : 0xFFFF0000u);
                    }
                    pl[mt][nn] = p01;
                    ph[mt][nn] = p23;
                }
            }
        }

        // O += P V ; lsc += P @ ones (row sums on the tensor pipe)
        #pragma unroll
        for (int t = 0; t < 4; t++) {
            const uint32_t pa0[4] = { pl[0][2*t], ph[0][2*t], pl[0][2*t+1], ph[0][2*t+1] };
            const uint32_t pa1[4] = { pl[1][2*t], ph[1][2*t], pl[1][2*t+1], ph[1][2*t+1] };
            mma_f16(lsc[0], pa0, one_b, one_b);
            mma_f16(lsc[1], pa1, one_b, one_b);
            #pragma unroll
            for (int np = 0; np < 4; np++) {
                uint32_t vr[4];
                ldsm4t(vr, addrT(Vb, lane, 16 * t, 16 * np));
                mma_f16(oc[0][2 * np],     pa0, vr[0], vr[1]);
                mma_f16(oc[0][2 * np + 1], pa0, vr[2], vr[3]);
                mma_f16(oc[1][2 * np],     pa1, vr[0], vr[1]);
                mma_f16(oc[1][2 * np + 1], pa1, vr[2], vr[3]);
            }
        }
    }

    // row sums live in col 0 of lsc on tig==0 lanes (lane 4g); broadcast.
    #pragma unroll
    for (int mt = 0; mt < 2; mt++) {
        const float s0 = __shfl_sync(0xffffffffu, lsc[mt][0], lane & 0x1c);
        const float s1 = __shfl_sync(0xffffffffu, lsc[mt][2], lane & 0x1c);
        const float inv0 = 1.0f / s0, inv1 = 1.0f / s1;
        const size_t ra = (size_t)(32 * w + 16 * mt + g);
        #pragma unroll
        for (int n = 0; n < 8; n++) {
            *(float2*)(out + qbase + ra * NH + 8 * n + 2 * tig) =
                make_float2(oc[mt][n][0] * inv0, oc[mt][n][1] * inv0);
            *(float2*)(out + qbase + (ra + 8) * NH + 8 * n + 2 * tig) =
                make_float2(oc[mt][n][2] * inv1, oc[mt][n][3] * inv1);
        }
    }
}

extern "C" void kernel_launch(void* const* d_in, const int* in_sizes, int n_in,
                              void* d_out, int out_size) {
    (void)in_sizes; (void)n_in; (void)out_size;
    const float* x  = (const float*)d_in[0];
    const float* wk = (const float*)d_in[1];
    const float* wq = (const float*)d_in[2];
    const float* wv = (const float*)d_in[3];
    float* out = (float*)d_out;

    cudaFuncSetAttribute(proj_kernel, cudaFuncAttributeMaxDynamicSharedMemorySize, SMEM1);
    cudaFuncSetAttribute(attn_kernel, cudaFuncAttributeMaxDynamicSharedMemorySize, SMEM2);

    proj_kernel<<<(NB * NT) / 256, 128, SMEM1>>>(x, wk, wq, wv);
    attn_kernel<<<dim3(NT / 128, NB), 128, SMEM2>>>(out);
}

// round 13
// speedup vs baseline: 1.0005x; 1.0005x over previous
#include <cuda_runtime.h>
#include <cuda_fp16.h>
#include <cstdint>

#define NB 256
#define NT 512
#define NC 64
#define NH 64
#define HP 72          // halves per smem row (pad: 144B rows, conflict-free ldmatrix)
#define HPB 144        // bytes per smem row

// Projected q,k,v scratch in fp16 (11-bit significand == tf32).
// q pre-scaled by 0.125*log2(e): softmax exp is ex2 (base-2 domain).
// g_q/g_k rows use a fragment-native WITHIN-ROW PERMUTATION (identical for
// both, so the QK contraction is unchanged). g_v stays logical row-major.
__device__ __half g_q[(size_t)NB * NT * NH];
__device__ __half g_k[(size_t)NB * NT * NH];
__device__ __half g_v[(size_t)NB * NT * NH];

__device__ __forceinline__ uint32_t smem_u32(const void* p) {
    uint32_t a;
    asm("{ .reg .u64 t; cvta.to.shared.u64 t, %1; cvt.u32.u64 %0, t; }"
        : "=r"(a) : "l"(p));
    return a;
}
__device__ __forceinline__ uint32_t packh2(float lo, float hi) {
    __half2 h = __floats2half2_rn(lo, hi);
    return *reinterpret_cast<uint32_t*>(&h);
}
__device__ __forceinline__ uint32_t ex2h2(uint32_t s) {   // 2 exps, 1 MUFU op
    uint32_t r;
    asm("ex2.approx.f16x2 %0, %1;" : "=r"(r) : "r"(s));
    return r;
}
__device__ __forceinline__ void mma_f16(float c[4], const uint32_t a[4],
                                        uint32_t b0, uint32_t b1) {
    asm volatile(
        "mma.sync.aligned.m16n8k16.row.col.f32.f16.f16.f32 "
        "{%0,%1,%2,%3}, {%4,%5,%6,%7}, {%8,%9}, {%0,%1,%2,%3};"
        : "+f"(c[0]), "+f"(c[1]), "+f"(c[2]), "+f"(c[3])
        : "r"(a[0]), "r"(a[1]), "r"(a[2]), "r"(a[3]), "r"(b0), "r"(b1));
}
__device__ __forceinline__ void ldsm4(uint32_t r[4], uint32_t addr) {
    asm volatile("ldmatrix.sync.aligned.m8n8.x4.shared.b16 {%0,%1,%2,%3}, [%4];"
        : "=r"(r[0]), "=r"(r[1]), "=r"(r[2]), "=r"(r[3]) : "r"(addr));
}
__device__ __forceinline__ void ldsm4t(uint32_t r[4], uint32_t addr) {
    asm volatile("ldmatrix.sync.aligned.m8n8.x4.trans.shared.b16 {%0,%1,%2,%3}, [%4];"
        : "=r"(r[0]), "=r"(r[1]), "=r"(r[2]), "=r"(r[3]) : "r"(addr));
}
// A (row-major m16k16): m0=(r0..7,k0..7) m1=(r8..15,k0..7) m2=(r0..7,k8..15) m3=(r8..15,k8..15)
__device__ __forceinline__ uint32_t addrA(uint32_t base, int lane, int row0, int k0) {
    return base + (uint32_t)(row0 + (lane & 15)) * HPB
                + (uint32_t)(k0 * 2 + ((lane >> 4) << 4));
}
// B from K rows (row-major [n][k], no trans)
__device__ __forceinline__ uint32_t addrB(uint32_t base, int lane, int n0, int k0) {
    return base + (uint32_t)(n0 + (lane & 7) + ((lane >> 4) << 3)) * HPB
                + (uint32_t)(k0 * 2 + (((lane >> 3) & 1) << 4));
}
// B from V/W rows (row-major [k][n], trans)
__device__ __forceinline__ uint32_t addrT(uint32_t base, int lane, int s0, int n0) {
    return base + (uint32_t)(s0 + (lane & 7) + (((lane >> 3) & 1) << 3)) * HPB
                + (uint32_t)(n0 * 2 + ((lane >> 4) << 4));
}
#define CP_ASYNC16(dst, src) \
    asm volatile("cp.async.cg.shared.global [%0], [%1], 16;" \
                 :: "r"((uint32_t)(dst)), "l"(src))
#define CP_COMMIT() asm volatile("cp.async.commit_group;" ::: "memory")
#define CP_WAIT0()  asm volatile("cp.async.wait_group 0;" ::: "memory")

__device__ __forceinline__ void load_tile64(uint32_t dst, const __half* src, int tid) {
    #pragma unroll
    for (int m = 0; m < 4; m++) {
        int idx = tid + 128 * m;
        int r = idx >> 3, c = idx & 7;
        CP_ASYNC16(dst + r * HPB + c * 16, src + r * NH + c * 8);
    }
}

// attn smem
#define K0OFF 0
#define K1OFF 9216
#define V0OFF 18432
#define V1OFF 27648
#define PQOFF 36864      // Q staging (frags lifted to regs once)
#define SMEM2 55296
// proj: x rows 0-127 (reused as V store staging), W_sel rows 128+64*sel
#define SMEM1 46080

// ---------------------------------------------------------------------------
// attn tile-phase helpers (fully unrolled straight-line bodies so ptxas can
// interleave the PV(j) and QK(j+1) MMA streams within one loop iteration).
// ---------------------------------------------------------------------------
__device__ __forceinline__ void qk_exp_tile(
    uint32_t Kb, const uint32_t (&qa)[2][4][4],
    uint32_t (&pl)[2][8], uint32_t (&ph)[2][8],
    int lane, int tig, int jbase, bool needMask, int row0q)
{
    #pragma unroll
    for (int np = 0; np < 4; np++) {
        float sc[2][2][4] = {};
        #pragma unroll
        for (int t = 0; t < 4; t++) {
            uint32_t kr[4];
            ldsm4(kr, addrB(Kb, lane, 16 * np, 16 * t));
            mma_f16(sc[0][0], qa[0][t], kr[0], kr[1]);
            mma_f16(sc[0][1], qa[0][t], kr[2], kr[3]);
            mma_f16(sc[1][0], qa[1][t], kr[0], kr[1]);
            mma_f16(sc[1][1], qa[1][t], kr[2], kr[3]);
        }
        #pragma unroll
        for (int mt = 0; mt < 2; mt++) {
            const int r0 = row0q + 16 * mt, r1 = r0 + 8;
            #pragma unroll
            for (int hh = 0; hh < 2; hh++) {
                const int nn = 2 * np + hh;
                const int col = jbase + 8 * nn + 2 * tig;
                uint32_t p01 = ex2h2(packh2(sc[mt][hh][0], sc[mt][hh][1]));
                uint32_t p23 = ex2h2(packh2(sc[mt][hh][2], sc[mt][hh][3]));
                if (needMask) {
                    p01 &= (col > r0 ? 0u : 0x0000FFFFu) |
                           (col + 1 > r0 ? 0u : 0xFFFF0000u);
                    p23 &= (col > r1 ? 0u : 0x0000FFFFu) |
                           (col + 1 > r1 ? 0u : 0xFFFF0000u);
                }
                pl[mt][nn] = p01;
                ph[mt][nn] = p23;
            }
        }
    }
}

__device__ __forceinline__ void pv_tile(
    uint32_t Vb, const uint32_t (&pl)[2][8], const uint32_t (&ph)[2][8],
    float (&oc)[2][8][4], float (&lsc)[2][4], int lane, uint32_t one_b)
{
    #pragma unroll
    for (int t = 0; t < 4; t++) {
        const uint32_t pa0[4] = { pl[0][2*t], ph[0][2*t], pl[0][2*t+1], ph[0][2*t+1] };
        const uint32_t pa1[4] = { pl[1][2*t], ph[1][2*t], pl[1][2*t+1], ph[1][2*t+1] };
        mma_f16(lsc[0], pa0, one_b, one_b);
        mma_f16(lsc[1], pa1, one_b, one_b);
        #pragma unroll
        for (int np = 0; np < 4; np++) {
            uint32_t vr[4];
            ldsm4t(vr, addrT(Vb, lane, 16 * t, 16 * np));
            mma_f16(oc[0][2 * np],     pa0, vr[0], vr[1]);
            mma_f16(oc[0][2 * np + 1], pa0, vr[2], vr[3]);
            mma_f16(oc[1][2 * np],     pa1, vr[0], vr[1]);
            mma_f16(oc[1][2 * np + 1], pa1, vr[2], vr[3]);
        }
    }
}

// ---------------------------------------------------------------------------
// Kernel 1: q,k,v = x @ {Wq,Wk,Wv}. 512 CTAs x two 128-row halves;
// W in smem once per CTA. Wq pre-scaled by 0.125*log2(e).
// Q/K stored with fragment-native within-row permutation (coalesced 16B
// stores); V restaged through the dead x smem region for coalesced stores.
// ---------------------------------------------------------------------------
__global__ void __launch_bounds__(128, 4) proj_kernel(
    const float* __restrict__ x,
    const float* __restrict__ wk,
    const float* __restrict__ wq,
    const float* __restrict__ wv)
{
    extern __shared__ char smraw[];
    __half* smh = (__half*)smraw;
    const uint32_t sb = smem_u32(smraw);
    const int tid = threadIdx.x;
    const int w = tid >> 5, lane = tid & 31, g = lane >> 2, tig = lane & 3;

    const float* W[3] = { wq, wk, wv };
    #pragma unroll
    for (int sel = 0; sel < 3; sel++) {
        __half* ws = smh + (128 + 64 * sel) * HP;
        const float scl = (sel == 0) ? 0.125f * 1.44269504088896f : 1.0f;
        #pragma unroll
        for (int m = 0; m < 8; m++) {
            int idx = tid + 128 * m;
            int r = idx >> 4, f4 = idx & 15;
            float4 v = *(const float4*)(W[sel] + r * NH + f4 * 4);
            *(__half2*)(ws + r * HP + f4 * 4)     = __floats2half2_rn(v.x * scl, v.y * scl);
            *(__half2*)(ws + r * HP + f4 * 4 + 2) = __floats2half2_rn(v.z * scl, v.w * scl);
        }
    }

    #pragma unroll 1
    for (int h = 0; h < 2; h++) {
        const size_t r0 = (size_t)blockIdx.x * 256 + (size_t)h * 128;
        __syncthreads();   // h=0: W ready; h>0: prior V-staging copies done
        #pragma unroll
        for (int m = 0; m < 16; m++) {
            int idx = tid + 128 * m;
            int r = idx >> 4, f4 = idx & 15;
            float4 v = *(const float4*)(x + (r0 + r) * NC + f4 * 4);
            *(__half2*)(smh + r * HP + f4 * 4)     = __floats2half2_rn(v.x, v.y);
            *(__half2*)(smh + r * HP + f4 * 4 + 2) = __floats2half2_rn(v.z, v.w);
        }
        __syncthreads();

        uint32_t xa[2][4][4];
        #pragma unroll
        for (int mt = 0; mt < 2; mt++)
            #pragma unroll
            for (int t = 0; t < 4; t++)
                ldsm4(xa[mt][t], addrA(sb, lane, 32 * w + 16 * mt, 16 * t));

        #pragma unroll
        for (int sel = 0; sel < 3; sel++) {
            const uint32_t wb = sb + (uint32_t)(128 + 64 * sel) * HPB;
            float cc[2][8][4] = {};
            #pragma unroll
            for (int t = 0; t < 4; t++)
                #pragma unroll
                for (int np = 0; np < 4; np++) {
                    uint32_t br[4];
                    ldsm4t(br, addrT(wb, lane, 16 * t, 16 * np));
                    #pragma unroll
                    for (int mt = 0; mt < 2; mt++) {
                        mma_f16(cc[mt][2 * np],     xa[mt][t], br[0], br[1]);
                        mma_f16(cc[mt][2 * np + 1], xa[mt][t], br[2], br[3]);
                    }
                }

            if (sel < 2) {
                // Q/K: permuted within-row layout -> coalesced 16B stores.
                __half* G = (sel == 0) ? g_q : g_k;
                #pragma unroll
                for (int mt = 0; mt < 2; mt++) {
                    const size_t ra = r0 + 32 * w + 16 * mt + g;
                    uint32_t lo[8], hi[8];
                    #pragma unroll
                    for (int n = 0; n < 8; n++) {
                        lo[n] = packh2(cc[mt][n][0], cc[mt][n][1]);
                        hi[n] = packh2(cc[mt][n][2], cc[mt][n][3]);
                    }
                    char* d0 = (char*)(G + ra * NH) + tig * 32;
                    char* d1 = (char*)(G + (ra + 8) * NH) + tig * 32;
                    *(uint4*)d0        = make_uint4(lo[0], lo[1], lo[2], lo[3]);
                    *(uint4*)(d0 + 16) = make_uint4(lo[4], lo[5], lo[6], lo[7]);
                    *(uint4*)d1        = make_uint4(hi[0], hi[1], hi[2], hi[3]);
                    *(uint4*)(d1 + 16) = make_uint4(hi[4], hi[5], hi[6], hi[7]);
                }
            } else {
                // V: logical layout; restage through dead x region.
                __syncthreads();
                #pragma unroll
                for (int mt = 0; mt < 2; mt++) {
                    const int rl = 32 * w + 16 * mt + g;
                    #pragma unroll
                    for (int n = 0; n < 8; n++) {
                        *(__half2*)(smh + rl * HP + 8 * n + 2 * tig) =
                            __floats2half2_rn(cc[mt][n][0], cc[mt][n][1]);
                        *(__half2*)(smh + (rl + 8) * HP + 8 * n + 2 * tig) =
                            __floats2half2_rn(cc[mt][n][2], cc[mt][n][3]);
                    }
                }
                __syncthreads();
                #pragma unroll
                for (int i = 0; i < 8; i++) {
                    int c = tid + 128 * i;
                    int r = c >> 3, o = c & 7;
                    uint4 val = *(uint4*)(smraw + r * HPB + o * 16);
                    *(uint4*)(g_v + (r0 + r) * NH + o * 8) = val;
                }
            }
        }
    }
}

// ---------------------------------------------------------------------------
// Kernel 2: flash attention — software-pipelined across key tiles:
// each iteration runs PV(j) and QK(j+1)+exp(j+1) back-to-back (independent
// MMA streams, interleaved by ptxas). Prologue QK(0); epilogue PV(nt-1).
// K buffered one tile ahead of V. Row sums on the tensor pipe (P @ ones).
// ---------------------------------------------------------------------------
__global__ void __launch_bounds__(128, 3) attn_kernel(float* __restrict__ out)
{
    extern __shared__ char smraw[];
    const uint32_t sb = smem_u32(smraw);
    const int tid = threadIdx.x;
    const int w = tid >> 5, lane = tid & 31, g = lane >> 2, tig = lane & 3;
    const int qt = (gridDim.x - 1) - blockIdx.x;   // big causal tiles first
    const int b = blockIdx.y;
    const int nt = 2 * qt + 2;
    const size_t qbase = ((size_t)b * NT + (size_t)qt * 128) * NH;
    const __half* kp0 = g_k + (size_t)b * NT * NH;
    const __half* vp0 = g_v + (size_t)b * NT * NH;

    // ones B-fragment (k16n8, column 0 all ones)
    const uint32_t one_b = (g == 0) ? 0x3C003C00u : 0u;

    // group 0: K(0), V(0)
    load_tile64(sb + K0OFF, kp0, tid);
    load_tile64(sb + V0OFF, vp0, tid);
    CP_COMMIT();

    // stage Q (fp16, pre-scaled, permuted rows copied verbatim)
    #pragma unroll
    for (int m = 0; m < 8; m++) {
        int idx = tid + 128 * m;
        int r = idx >> 3, c = idx & 7;
        *(uint4*)(smraw + PQOFF + r * HPB + c * 16) =
            *(const uint4*)(g_q + qbase + r * NH + c * 8);
    }
    CP_WAIT0();
    __syncthreads();   // Q staged, K0/V0 resident

    uint32_t qa[2][4][4];
    #pragma unroll
    for (int mt = 0; mt < 2; mt++)
        #pragma unroll
        for (int t = 0; t < 4; t++)
            ldsm4(qa[mt][t], addrA(sb + PQOFF, lane, 32 * w + 16 * mt, 16 * t));

    // prefetch K(1) while computing QK(0)
    load_tile64(sb + K1OFF, kp0 + (size_t)64 * NH, tid);
    CP_COMMIT();

    float oc[2][8][4] = {};
    float lsc[2][4] = {};
    uint32_t pl[2][8], ph[2][8];
    const int row0q = qt * 128 + 32 * w + g;

    // prologue: QK(0) + exp(0)  (mask only if tile 0 is diagonal, i.e. qt==0)
    qk_exp_tile(sb + K0OFF, qa, pl, ph, lane, tig, 0, (0 >= 2 * qt), row0q);

    for (int j = 0; j + 1 < nt; j++) {
        CP_WAIT0();        // K(j+1) and V(j) resident
        __syncthreads();   // all warps done with buffers being overwritten
        if (j + 2 < nt)
            load_tile64(sb + ((j & 1) ? K1OFF : K0OFF),
                        kp0 + (size_t)(j + 2) * 64 * NH, tid);
        load_tile64(sb + (((j + 1) & 1) ? V1OFF : V0OFF),
                    vp0 + (size_t)(j + 1) * 64 * NH, tid);
        CP_COMMIT();

        // PV(j) — consumes pl/ph of tile j and V(j)
        pv_tile(sb + ((j & 1) ? V1OFF : V0OFF), pl, ph, oc, lsc, lane, one_b);
        // QK(j+1) + exp — overwrites pl/ph with tile j+1's P
        const int jj = j + 1;
        qk_exp_tile(sb + ((jj & 1) ? K1OFF : K0OFF), qa, pl, ph,
                    lane, tig, jj * 64, (jj >= 2 * qt), row0q);
    }

    CP_WAIT0();
    __syncthreads();   // V(nt-1) resident
    pv_tile(sb + (((nt - 1) & 1) ? V1OFF : V0OFF), pl, ph, oc, lsc, lane, one_b);

    // row sums live in col 0 of lsc on tig==0 lanes (lane 4g); broadcast.
    #pragma unroll
    for (int mt = 0; mt < 2; mt++) {
        const float s0 = __shfl_sync(0xffffffffu, lsc[mt][0], lane & 0x1c);
        const float s1 = __shfl_sync(0xffffffffu, lsc[mt][2], lane & 0x1c);
        const float inv0 = 1.0f / s0, inv1 = 1.0f / s1;
        const size_t ra = (size_t)(32 * w + 16 * mt + g);
        #pragma unroll
        for (int n = 0; n < 8; n++) {
            *(float2*)(out + qbase + ra * NH + 8 * n + 2 * tig) =
                make_float2(oc[mt][n][0] * inv0, oc[mt][n][1] * inv0);
            *(float2*)(out + qbase + (ra + 8) * NH + 8 * n + 2 * tig) =
                make_float2(oc[mt][n][2] * inv1, oc[mt][n][3] * inv1);
        }
    }
}

extern "C" void kernel_launch(void* const* d_in, const int* in_sizes, int n_in,
                              void* d_out, int out_size) {
    (void)in_sizes; (void)n_in; (void)out_size;
    const float* x  = (const float*)d_in[0];
    const float* wk = (const float*)d_in[1];
    const float* wq = (const float*)d_in[2];
    const float* wv = (const float*)d_in[3];
    float* out = (float*)d_out;

    cudaFuncSetAttribute(proj_kernel, cudaFuncAttributeMaxDynamicSharedMemorySize, SMEM1);
    cudaFuncSetAttribute(attn_kernel, cudaFuncAttributeMaxDynamicSharedMemorySize, SMEM2);

    proj_kernel<<<(NB * NT) / 256, 128, SMEM1>>>(x, wk, wq, wv);
    attn_kernel<<<dim3(NT / 128, NB), 128, SMEM2>>>(out);
}